// round 8
// baseline (speedup 1.0000x reference)
#include <cuda_runtime.h>

#define BB 2
#define CC 64
#define NN 16384
#define KK 16
#define COUT 64

// Scratch (static device globals — no allocation allowed)
__device__ float g_y1[BB * NN * CC];    // (W1-W2)·x, node-major [b][n][o]
__device__ float g_y2[BB * NN * CC];    // W2·x,      node-major [b][n][o]
__device__ float g_mean[BB * CC];       // per-batch channel means
__device__ float g_dvec[BB * COUT];     // W3·mean + bias

// ---------------------------------------------------------------------------
// Kernel 1: per-(b,c) mean over nodes. 128 blocks x 256 threads.
// ---------------------------------------------------------------------------
__global__ void mean_kernel(const float* __restrict__ x) {
    int row = blockIdx.x;                       // b*64 + c
    const float* p = x + (size_t)row * NN;
    float s = 0.f;
    for (int i = threadIdx.x; i < NN; i += 256) s += p[i];
    for (int off = 16; off; off >>= 1) s += __shfl_down_sync(0xffffffffu, s, off);
    __shared__ float red[8];
    if ((threadIdx.x & 31) == 0) red[threadIdx.x >> 5] = s;
    __syncthreads();
    if (threadIdx.x < 8) {
        s = red[threadIdx.x];
        for (int off = 4; off; off >>= 1) s += __shfl_down_sync(0xffu, s, off);
        if (threadIdx.x == 0) g_mean[row] = s * (1.f / NN);
    }
}

// ---------------------------------------------------------------------------
// Kernel 2: d[b][o] = bias[o] + sum_c W3[o][c] * mean[b][c]. 1 block, 128 thr.
// ---------------------------------------------------------------------------
__global__ void dvec_kernel(const float* __restrict__ W, const float* __restrict__ bias) {
    int t = threadIdx.x;
    if (t >= BB * COUT) return;
    int b = t >> 6, o = t & 63;
    float s = bias[o];
#pragma unroll 8
    for (int c = 0; c < CC; c++)
        s += W[o * 192 + 128 + c] * g_mean[b * CC + c];
    g_dvec[t] = s;
}

// ---------------------------------------------------------------------------
// Kernel 3 (v2): y1/y2 GEMM. 64-node tiles, grid 512, 4 blocks/SM.
// Weights stored transposed [c][o] in smem so every inner-loop smem access is
// a float4 (x: 1 LDS.128; wa/wb: broadcast LDS.128). 16 node-lanes x 4 nodes,
// 16 o-groups x 4 outs. FMA-bound: ~4096 cyc/block.
// ---------------------------------------------------------------------------
__global__ void __launch_bounds__(256, 4) gemm_kernel(const float* __restrict__ x,
                                                      const float* __restrict__ W) {
    __shared__ float xs[64 * 64];    // [c][node]  16KB
    __shared__ float wa[64 * 64];    // [c][o]     16KB  (W1-W2, transposed)
    __shared__ float wb[64 * 64];    // [c][o]     16KB  (W2, transposed)

    int b  = blockIdx.x >> 8;        // 256 tiles per batch
    int n0 = (blockIdx.x & 255) << 6;
    int tid = threadIdx.x;

    for (int i = tid; i < 64 * 64; i += 256) {
        int c = i >> 6, o = i & 63;
        float w2 = W[o * 192 + 64 + c];
        wa[c * 64 + o] = W[o * 192 + c] - w2;
        wb[c * 64 + o] = w2;
    }
    const float* xb = x + (size_t)b * CC * NN + n0;
    for (int i = tid; i < 64 * 64; i += 256) {
        int c = i >> 6, nl = i & 63;
        xs[i] = xb[(size_t)c * NN + nl];    // coalesced 64-float rows
    }
    __syncthreads();

    int nl4 = (tid & 15) * 4;        // 4 consecutive nodes
    int o0  = (tid >> 4) * 4;        // 4 outputs

    float a1[4][4], a2[4][4];        // [node][out]
#pragma unroll
    for (int q = 0; q < 4; q++)
#pragma unroll
        for (int j = 0; j < 4; j++) { a1[q][j] = 0.f; a2[q][j] = 0.f; }

#pragma unroll 2
    for (int c = 0; c < 64; c++) {
        float4 xv  = *(const float4*)&xs[c * 64 + nl4];
        float4 wav = *(const float4*)&wa[c * 64 + o0];
        float4 wbv = *(const float4*)&wb[c * 64 + o0];
        const float xq[4] = {xv.x, xv.y, xv.z, xv.w};
        const float waj[4] = {wav.x, wav.y, wav.z, wav.w};
        const float wbj[4] = {wbv.x, wbv.y, wbv.z, wbv.w};
#pragma unroll
        for (int q = 0; q < 4; q++)
#pragma unroll
            for (int j = 0; j < 4; j++) {
                a1[q][j] += xq[q] * waj[j];
                a2[q][j] += xq[q] * wbj[j];
            }
    }

#pragma unroll
    for (int q = 0; q < 4; q++) {
        size_t base = ((size_t)b * NN + n0 + nl4 + q) * 64 + o0;
        *(float4*)&g_y1[base] = make_float4(a1[q][0], a1[q][1], a1[q][2], a1[q][3]);
        *(float4*)&g_y2[base] = make_float4(a2[q][0], a2[q][1], a2[q][2], a2[q][3]);
    }
}

// ---------------------------------------------------------------------------
// Kernel 4 (v3): gather + max over K + dvec + relu. float4 loads, 32-node
// tiles -> grid 1024, launch_bounds(256,6) caps regs ~42 -> occ ~75%
// (R7 showed occ reg-limited at 45%, L2 only 45% => raise concurrency).
// #pragma unroll 4 on K bounds live loads to fit the reg cap without spills.
// ---------------------------------------------------------------------------
__global__ void __launch_bounds__(256, 6) gather_kernel(const int* __restrict__ ei,
                                                        float* __restrict__ out) {
    __shared__ int   s_j0[32 * KK];
    __shared__ int   s_j1[32 * KK];
    __shared__ float s_out[64][34];     // [channel][node], padded

    int b   = blockIdx.x >> 9;          // 512 tiles per batch
    int n0  = (blockIdx.x & 511) << 5;
    int tid = threadIdx.x;

    const int* e0 = ei + ((size_t)b * NN + n0) * KK;            // neighbors (edge_index[0])
    const int* e1 = ei + ((size_t)(BB + b) * NN + n0) * KK;     // centers   (edge_index[1])
    for (int i = tid; i < 32 * KK; i += 256) {
        s_j0[i] = (e0[i] & (NN - 1)) << 4;   // float4-row offset
        s_j1[i] = (e1[i] & (NN - 1)) << 4;
    }
    __syncthreads();

    int f4 = tid & 15;                  // which float4 of the 64-channel row
    int ng = tid >> 4;                  // node group 0..15 (2 nodes each)
    const float4* y1 = (const float4*)g_y1 + (size_t)b * NN * 16;
    const float4* y2 = (const float4*)g_y2 + (size_t)b * NN * 16;

#pragma unroll
    for (int nl = ng; nl < 32; nl += 16) {
        float4 m = make_float4(-3.4e38f, -3.4e38f, -3.4e38f, -3.4e38f);
        const int* pj1 = &s_j1[nl * KK];
        const int* pj0 = &s_j0[nl * KK];
#pragma unroll 4
        for (int k = 0; k < KK; k++) {
            float4 a = __ldg(y1 + pj1[k] + f4);
            float4 c = __ldg(y2 + pj0[k] + f4);
            m.x = fmaxf(m.x, a.x + c.x);
            m.y = fmaxf(m.y, a.y + c.y);
            m.z = fmaxf(m.z, a.z + c.z);
            m.w = fmaxf(m.w, a.w + c.w);
        }
        int o0 = f4 * 4;
        s_out[o0 + 0][nl] = m.x;
        s_out[o0 + 1][nl] = m.y;
        s_out[o0 + 2][nl] = m.z;
        s_out[o0 + 3][nl] = m.w;
    }
    __syncthreads();

    float* ob = out + (size_t)b * COUT * NN + n0;
    for (int i = tid; i < 64 * 8; i += 256) {        // 64 channels x 8 float4
        int o2 = i >> 3, q = i & 7;
        float d = g_dvec[b * 64 + o2];
        int nb = q * 4;
        float4 v;
        v.x = fmaxf(s_out[o2][nb + 0] + d, 0.f);
        v.y = fmaxf(s_out[o2][nb + 1] + d, 0.f);
        v.z = fmaxf(s_out[o2][nb + 2] + d, 0.f);
        v.w = fmaxf(s_out[o2][nb + 3] + d, 0.f);
        *(float4*)(ob + (size_t)o2 * NN + nb) = v;   // n0 mult of 32 -> 16B aligned
    }
}

// ---------------------------------------------------------------------------
extern "C" void kernel_launch(void* const* d_in, const int* in_sizes, int n_in,
                              void* d_out, int out_size) {
    const float* x    = (const float*)d_in[0];
    const int*   ei   = (const int*)d_in[1];
    const float* W    = (const float*)d_in[2];
    const float* bias = (const float*)d_in[3];
    float*       out  = (float*)d_out;

    mean_kernel<<<BB * CC, 256>>>(x);
    dvec_kernel<<<1, 128>>>(W, bias);
    gemm_kernel<<<BB * (NN / 64), 256>>>(x, W);
    gather_kernel<<<BB * (NN / 32), 256>>>(ei, out);
}

// round 12
// speedup vs baseline: 1.5056x; 1.5056x over previous
#include <cuda_runtime.h>
#include <cuda_fp16.h>

#define BB 2
#define CC 64
#define NN 16384
#define KK 16
#define COUT 64

// Scratch (static device globals — no allocation allowed)
__device__ __half g_y1h[BB * NN * CC];   // (W1-W2)·x, node-major [b][n][o], fp16
__device__ __half g_y2h[BB * NN * CC];   // W2·x,      node-major [b][n][o], fp16
__device__ float  g_mean[BB * CC];       // per-batch channel means
__device__ float  g_dvec[BB * COUT];     // W3·mean + bias

// ---------------------------------------------------------------------------
// Kernel 1: per-(b,c) mean over nodes. 128 blocks x 256 threads.
// ---------------------------------------------------------------------------
__global__ void mean_kernel(const float* __restrict__ x) {
    int row = blockIdx.x;                       // b*64 + c
    const float* p = x + (size_t)row * NN;
    float s = 0.f;
    for (int i = threadIdx.x; i < NN; i += 256) s += p[i];
    for (int off = 16; off; off >>= 1) s += __shfl_down_sync(0xffffffffu, s, off);
    __shared__ float red[8];
    if ((threadIdx.x & 31) == 0) red[threadIdx.x >> 5] = s;
    __syncthreads();
    if (threadIdx.x < 8) {
        s = red[threadIdx.x];
        for (int off = 4; off; off >>= 1) s += __shfl_down_sync(0xffu, s, off);
        if (threadIdx.x == 0) g_mean[row] = s * (1.f / NN);
    }
}

// ---------------------------------------------------------------------------
// Kernel 2: d[b][o] = bias[o] + sum_c W3[o][c] * mean[b][c]. 1 block, 128 thr.
// ---------------------------------------------------------------------------
__global__ void dvec_kernel(const float* __restrict__ W, const float* __restrict__ bias) {
    int t = threadIdx.x;
    if (t >= BB * COUT) return;
    int b = t >> 6, o = t & 63;
    float s = bias[o];
#pragma unroll 8
    for (int c = 0; c < CC; c++)
        s += W[o * 192 + 128 + c] * g_mean[b * CC + c];
    g_dvec[t] = s;
}

// ---------------------------------------------------------------------------
// Kernel 3: y1/y2 GEMM (proven v1 shape), fp16 output.
// 128-node tiles, 256 threads = 8 o-groups(8 outs) x 32 node-lanes, 4
// nodes/thread. Dynamic smem 64KB. Stores packed half2 (one uint4 = 8 halves
// per table per node).
// ---------------------------------------------------------------------------
__global__ void __launch_bounds__(256, 1) gemm_kernel(const float* __restrict__ x,
                                                      const float* __restrict__ W) {
    extern __shared__ float sm[];
    float* xs = sm;                 // [64][128]  x tile (c-major)
    float* wa = sm + 64 * 128;      // [64][64]   W1-W2
    float* wb = wa + 64 * 64;       // [64][64]   W2

    int b  = blockIdx.x >> 7;       // 128 tiles per batch
    int n0 = (blockIdx.x & 127) << 7;
    int tid = threadIdx.x;

    for (int i = tid; i < 64 * 64; i += 256) {
        int o = i >> 6, c = i & 63;
        float w2 = W[o * 192 + 64 + c];
        wa[i] = W[o * 192 + c] - w2;
        wb[i] = w2;
    }
    const float* xb = x + (size_t)b * CC * NN + n0;
    for (int i = tid; i < 64 * 128; i += 256) {
        int c = i >> 7, nl = i & 127;
        xs[i] = xb[(size_t)c * NN + nl];    // coalesced 128-float rows
    }
    __syncthreads();

    int nl = tid & 31;              // node lane (handles nl, nl+32, nl+64, nl+96)
    int o0 = (tid >> 5) * 8;        // 8 outputs per thread

    float a1[4][8], a2[4][8];
#pragma unroll
    for (int q = 0; q < 4; q++)
#pragma unroll
        for (int j = 0; j < 8; j++) { a1[q][j] = 0.f; a2[q][j] = 0.f; }

    for (int c = 0; c < 64; c++) {
        float xv[4];
#pragma unroll
        for (int q = 0; q < 4; q++) xv[q] = xs[c * 128 + nl + q * 32];
#pragma unroll
        for (int j = 0; j < 8; j++) {
            float wav = wa[(o0 + j) * 64 + c];   // broadcast within warp
            float wbv = wb[(o0 + j) * 64 + c];
#pragma unroll
            for (int q = 0; q < 4; q++) {
                a1[q][j] += wav * xv[q];
                a2[q][j] += wbv * xv[q];
            }
        }
    }

#pragma unroll
    for (int q = 0; q < 4; q++) {
        size_t base = ((size_t)b * NN + n0 + nl + q * 32) * 64 + o0;
        uint4 v1, v2;
        __half2 p10 = __floats2half2_rn(a1[q][0], a1[q][1]);
        __half2 p11 = __floats2half2_rn(a1[q][2], a1[q][3]);
        __half2 p12 = __floats2half2_rn(a1[q][4], a1[q][5]);
        __half2 p13 = __floats2half2_rn(a1[q][6], a1[q][7]);
        v1.x = *(unsigned*)&p10; v1.y = *(unsigned*)&p11;
        v1.z = *(unsigned*)&p12; v1.w = *(unsigned*)&p13;
        __half2 p20 = __floats2half2_rn(a2[q][0], a2[q][1]);
        __half2 p21 = __floats2half2_rn(a2[q][2], a2[q][3]);
        __half2 p22 = __floats2half2_rn(a2[q][4], a2[q][5]);
        __half2 p23 = __floats2half2_rn(a2[q][6], a2[q][7]);
        v2.x = *(unsigned*)&p20; v2.y = *(unsigned*)&p21;
        v2.z = *(unsigned*)&p22; v2.w = *(unsigned*)&p23;
        *(uint4*)&g_y1h[base] = v1;      // o0 mult of 8 -> 16B aligned
        *(uint4*)&g_y2h[base] = v2;
    }
}

// ---------------------------------------------------------------------------
// Kernel 4: gather + max over K + dvec + relu — fp16 tables.
// Gather traffic halved vs fp32 (R8 showed gather at ~90% of LTS cap: BYTES
// are the binder). 64-node tile, 256 threads = 16 uint2-lanes (8B = 4 ch)
// x 16 node groups. One 128B line per edge per table. HADD2/HMAX2 hot loop,
// float conversion only at the smem stage.
// ---------------------------------------------------------------------------
__global__ void __launch_bounds__(256, 6) gather_kernel(const int* __restrict__ ei,
                                                        float* __restrict__ out) {
    __shared__ int   s_j0[64 * KK];
    __shared__ int   s_j1[64 * KK];
    __shared__ float s_out[64][66];     // [channel][node], padded

    int b   = blockIdx.x >> 8;          // 256 tiles per batch
    int n0  = (blockIdx.x & 255) << 6;
    int tid = threadIdx.x;

    const int* e0 = ei + ((size_t)b * NN + n0) * KK;            // neighbors (edge_index[0])
    const int* e1 = ei + ((size_t)(BB + b) * NN + n0) * KK;     // centers   (edge_index[1])
    for (int i = tid; i < 64 * KK; i += 256) {
        s_j0[i] = (e0[i] & (NN - 1)) << 4;   // uint2-row offset (row = 16 uint2)
        s_j1[i] = (e1[i] & (NN - 1)) << 4;
    }
    __syncthreads();

    int f4 = tid & 15;                  // which uint2 (4 halves) of the row
    int ng = tid >> 4;                  // node group 0..15 (4 nodes each)
    const uint2* y1 = (const uint2*)g_y1h + (size_t)b * NN * 16;
    const uint2* y2 = (const uint2*)g_y2h + (size_t)b * NN * 16;

    const __half2 NEG = __float2half2_rn(-60000.f);

#pragma unroll
    for (int nl = ng; nl < 64; nl += 16) {
        __half2 m0 = NEG, m1 = NEG;
        const int* pj1 = &s_j1[nl * KK];
        const int* pj0 = &s_j0[nl * KK];
#pragma unroll
        for (int k = 0; k < KK; k++) {
            uint2 r1 = __ldg(y1 + pj1[k] + f4);
            uint2 r0 = __ldg(y2 + pj0[k] + f4);
            __half2 a0 = *(__half2*)&r1.x, a1 = *(__half2*)&r1.y;
            __half2 c0 = *(__half2*)&r0.x, c1 = *(__half2*)&r0.y;
            m0 = __hmax2(m0, __hadd2(a0, c0));
            m1 = __hmax2(m1, __hadd2(a1, c1));
        }
        float2 f0 = __half22float2(m0);
        float2 f1 = __half22float2(m1);
        int o0 = f4 * 4;
        s_out[o0 + 0][nl] = f0.x;
        s_out[o0 + 1][nl] = f0.y;
        s_out[o0 + 2][nl] = f1.x;
        s_out[o0 + 3][nl] = f1.y;
    }
    __syncthreads();

    float* ob = out + (size_t)b * COUT * NN + n0;
    for (int i = tid; i < 64 * 16; i += 256) {       // 64 channels x 16 float4
        int o2 = i >> 4, q = i & 15;
        float d = g_dvec[b * 64 + o2];
        int nb = q * 4;
        float4 v;
        v.x = fmaxf(s_out[o2][nb + 0] + d, 0.f);
        v.y = fmaxf(s_out[o2][nb + 1] + d, 0.f);
        v.z = fmaxf(s_out[o2][nb + 2] + d, 0.f);
        v.w = fmaxf(s_out[o2][nb + 3] + d, 0.f);
        *(float4*)(ob + (size_t)o2 * NN + nb) = v;   // n0 mult of 64 -> 16B aligned
    }
}

// ---------------------------------------------------------------------------
extern "C" void kernel_launch(void* const* d_in, const int* in_sizes, int n_in,
                              void* d_out, int out_size) {
    const float* x    = (const float*)d_in[0];
    const int*   ei   = (const int*)d_in[1];
    const float* W    = (const float*)d_in[2];
    const float* bias = (const float*)d_in[3];
    float*       out  = (float*)d_out;

    cudaFuncSetAttribute(gemm_kernel, cudaFuncAttributeMaxDynamicSharedMemorySize, 65536);

    mean_kernel<<<BB * CC, 256>>>(x);
    dvec_kernel<<<1, 128>>>(W, bias);
    gemm_kernel<<<BB * (NN / 128), 256, 65536>>>(x, W);
    gather_kernel<<<BB * (NN / 64), 256>>>(ei, out);
}

// round 13
// speedup vs baseline: 1.5721x; 1.0441x over previous
#include <cuda_runtime.h>
#include <cuda_fp16.h>

#define BB 2
#define CC 64
#define NN 16384
#define KK 16
#define COUT 64

// Scratch (static device globals — no allocation allowed)
__device__ __half g_y1h[BB * NN * CC];   // (W1-W2)·x, node-major [b][n][o], fp16
__device__ __half g_y2h[BB * NN * CC];   // W2·x,      node-major [b][n][o], fp16
__device__ float  g_mean[BB * CC];       // per-batch channel means
__device__ float  g_dvec[BB * COUT];     // W3·mean + bias

// ---------------------------------------------------------------------------
// Kernel 1: per-(b,c) mean over nodes. 128 blocks x 256 threads.
// ---------------------------------------------------------------------------
__global__ void mean_kernel(const float* __restrict__ x) {
    int row = blockIdx.x;                       // b*64 + c
    const float* p = x + (size_t)row * NN;
    float s = 0.f;
    for (int i = threadIdx.x; i < NN; i += 256) s += p[i];
    for (int off = 16; off; off >>= 1) s += __shfl_down_sync(0xffffffffu, s, off);
    __shared__ float red[8];
    if ((threadIdx.x & 31) == 0) red[threadIdx.x >> 5] = s;
    __syncthreads();
    if (threadIdx.x < 8) {
        s = red[threadIdx.x];
        for (int off = 4; off; off >>= 1) s += __shfl_down_sync(0xffu, s, off);
        if (threadIdx.x == 0) g_mean[row] = s * (1.f / NN);
    }
}

// ---------------------------------------------------------------------------
// Kernel 2: d[b][o] = bias[o] + sum_c W3[o][c] * mean[b][c]. 1 block, 128 thr.
// ---------------------------------------------------------------------------
__global__ void dvec_kernel(const float* __restrict__ W, const float* __restrict__ bias) {
    int t = threadIdx.x;
    if (t >= BB * COUT) return;
    int b = t >> 6, o = t & 63;
    float s = bias[o];
#pragma unroll 8
    for (int c = 0; c < CC; c++)
        s += W[o * 192 + 128 + c] * g_mean[b * CC + c];
    g_dvec[t] = s;
}

// ---------------------------------------------------------------------------
// Kernel 3 (f32x2): y1/y2 GEMM, fp16 output, packed fma.rn.f32x2.
// Both tables' accumulators live in ONE 64-bit lane: acc = {a1, a2}.
// Per c-iter: 4 LDS.32 (x) + 4 pack + 8 broadcast LDS.64 (w-pair) + 32 FMA2
// vs v1's 20 LDS + 64 FFMA — halves the instruction stream at identical
// fp32 precision. 128-node tiles, 256 thr = 8 o-groups x 32 node-lanes,
// 4 nodes/thread. smem: xs 32KB + wab 32KB = 64KB dynamic.
// ---------------------------------------------------------------------------
__global__ void __launch_bounds__(256, 1) gemm_kernel(const float* __restrict__ x,
                                                      const float* __restrict__ W) {
    extern __shared__ float sm[];
    float*  xs  = sm;                        // [64][128]  x tile (c-major)
    float2* wab = (float2*)(sm + 64 * 128);  // [o][c] -> {W1-W2, W2}

    int b  = blockIdx.x >> 7;       // 128 tiles per batch
    int n0 = (blockIdx.x & 127) << 7;
    int tid = threadIdx.x;

    for (int i = tid; i < 64 * 64; i += 256) {
        int o = i >> 6, c = i & 63;
        float w2 = W[o * 192 + 64 + c];
        wab[i] = make_float2(W[o * 192 + c] - w2, w2);
    }
    const float* xb = x + (size_t)b * CC * NN + n0;
    for (int i = tid; i < 64 * 128; i += 256) {
        int c = i >> 7, nl = i & 127;
        xs[i] = xb[(size_t)c * NN + nl];    // coalesced 128-float rows
    }
    __syncthreads();

    int nl = tid & 31;              // node lane (handles nl, nl+32, nl+64, nl+96)
    int o0 = (tid >> 5) * 8;        // 8 outputs per thread

    unsigned long long acc[4][8];   // packed {a1, a2} fp32 pairs
#pragma unroll
    for (int q = 0; q < 4; q++)
#pragma unroll
        for (int j = 0; j < 8; j++) acc[q][j] = 0ull;

    for (int c = 0; c < 64; c++) {
        unsigned long long xp[4];
#pragma unroll
        for (int q = 0; q < 4; q++) {
            float xv = xs[c * 128 + nl + q * 32];
            asm("mov.b64 %0, {%1, %1};" : "=l"(xp[q]) : "f"(xv));
        }
#pragma unroll
        for (int j = 0; j < 8; j++) {
            unsigned long long wp =
                *(const unsigned long long*)&wab[(o0 + j) * 64 + c];  // broadcast
#pragma unroll
            for (int q = 0; q < 4; q++)
                asm("fma.rn.f32x2 %0, %1, %2, %0;"
                    : "+l"(acc[q][j]) : "l"(wp), "l"(xp[q]));
        }
    }

#pragma unroll
    for (int q = 0; q < 4; q++) {
        float a1[8], a2[8];
#pragma unroll
        for (int j = 0; j < 8; j++)
            asm("mov.b64 {%0, %1}, %2;" : "=f"(a1[j]), "=f"(a2[j]) : "l"(acc[q][j]));
        size_t base = ((size_t)b * NN + n0 + nl + q * 32) * 64 + o0;
        uint4 v1, v2;
        __half2 p10 = __floats2half2_rn(a1[0], a1[1]);
        __half2 p11 = __floats2half2_rn(a1[2], a1[3]);
        __half2 p12 = __floats2half2_rn(a1[4], a1[5]);
        __half2 p13 = __floats2half2_rn(a1[6], a1[7]);
        v1.x = *(unsigned*)&p10; v1.y = *(unsigned*)&p11;
        v1.z = *(unsigned*)&p12; v1.w = *(unsigned*)&p13;
        __half2 p20 = __floats2half2_rn(a2[0], a2[1]);
        __half2 p21 = __floats2half2_rn(a2[2], a2[3]);
        __half2 p22 = __floats2half2_rn(a2[4], a2[5]);
        __half2 p23 = __floats2half2_rn(a2[6], a2[7]);
        v2.x = *(unsigned*)&p20; v2.y = *(unsigned*)&p21;
        v2.z = *(unsigned*)&p22; v2.w = *(unsigned*)&p23;
        *(uint4*)&g_y1h[base] = v1;      // o0 mult of 8 -> 16B aligned
        *(uint4*)&g_y2h[base] = v2;
    }
}

// ---------------------------------------------------------------------------
// Kernel 4 (v5): gather + max over K + dvec + relu — fp16 tables, 32-node
// tiles. R12 showed occ 46% (grid 512 -> 3.5 blocks/SM) with L2 at only
// ~60% of achievable: concurrency-starved. 32-node tiles double the grid to
// 1024 and launch_bounds(256,6) -> ~75% occ. 16 uint2-lanes x 16 groups,
// HADD2/HMAX2 hot loop, one 128B line per edge per table.
// ---------------------------------------------------------------------------
__global__ void __launch_bounds__(256, 6) gather_kernel(const int* __restrict__ ei,
                                                        float* __restrict__ out) {
    __shared__ int   s_j0[32 * KK];
    __shared__ int   s_j1[32 * KK];
    __shared__ float s_out[64][34];     // [channel][node], padded

    int b   = blockIdx.x >> 9;          // 512 tiles per batch
    int n0  = (blockIdx.x & 511) << 5;
    int tid = threadIdx.x;

    const int* e0 = ei + ((size_t)b * NN + n0) * KK;            // neighbors (edge_index[0])
    const int* e1 = ei + ((size_t)(BB + b) * NN + n0) * KK;     // centers   (edge_index[1])
    for (int i = tid; i < 32 * KK; i += 256) {
        s_j0[i] = (e0[i] & (NN - 1)) << 4;   // uint2-row offset (row = 16 uint2)
        s_j1[i] = (e1[i] & (NN - 1)) << 4;
    }
    __syncthreads();

    int f4 = tid & 15;                  // which uint2 (4 halves) of the row
    int ng = tid >> 4;                  // node group 0..15 (2 nodes each)
    const uint2* y1 = (const uint2*)g_y1h + (size_t)b * NN * 16;
    const uint2* y2 = (const uint2*)g_y2h + (size_t)b * NN * 16;

    const __half2 NEG = __float2half2_rn(-60000.f);

#pragma unroll
    for (int nl = ng; nl < 32; nl += 16) {
        __half2 m0 = NEG, m1 = NEG;
        const int* pj1 = &s_j1[nl * KK];
        const int* pj0 = &s_j0[nl * KK];
#pragma unroll
        for (int k = 0; k < KK; k++) {
            uint2 r1 = __ldg(y1 + pj1[k] + f4);
            uint2 r0 = __ldg(y2 + pj0[k] + f4);
            __half2 a0 = *(__half2*)&r1.x, a1 = *(__half2*)&r1.y;
            __half2 c0 = *(__half2*)&r0.x, c1 = *(__half2*)&r0.y;
            m0 = __hmax2(m0, __hadd2(a0, c0));
            m1 = __hmax2(m1, __hadd2(a1, c1));
        }
        float2 f0 = __half22float2(m0);
        float2 f1 = __half22float2(m1);
        int o0 = f4 * 4;
        s_out[o0 + 0][nl] = f0.x;
        s_out[o0 + 1][nl] = f0.y;
        s_out[o0 + 2][nl] = f1.x;
        s_out[o0 + 3][nl] = f1.y;
    }
    __syncthreads();

    float* ob = out + (size_t)b * COUT * NN + n0;
    for (int i = tid; i < 64 * 8; i += 256) {        // 64 channels x 8 float4
        int o2 = i >> 3, q = i & 7;
        float d = g_dvec[b * 64 + o2];
        int nb = q * 4;
        float4 v;
        v.x = fmaxf(s_out[o2][nb + 0] + d, 0.f);
        v.y = fmaxf(s_out[o2][nb + 1] + d, 0.f);
        v.z = fmaxf(s_out[o2][nb + 2] + d, 0.f);
        v.w = fmaxf(s_out[o2][nb + 3] + d, 0.f);
        *(float4*)(ob + (size_t)o2 * NN + nb) = v;   // n0 mult of 32 -> 16B aligned
    }
}

// ---------------------------------------------------------------------------
extern "C" void kernel_launch(void* const* d_in, const int* in_sizes, int n_in,
                              void* d_out, int out_size) {
    const float* x    = (const float*)d_in[0];
    const int*   ei   = (const int*)d_in[1];
    const float* W    = (const float*)d_in[2];
    const float* bias = (const float*)d_in[3];
    float*       out  = (float*)d_out;

    cudaFuncSetAttribute(gemm_kernel, cudaFuncAttributeMaxDynamicSharedMemorySize, 65536);

    mean_kernel<<<BB * CC, 256>>>(x);
    dvec_kernel<<<1, 128>>>(W, bias);
    gemm_kernel<<<BB * (NN / 128), 256, 65536>>>(x, W);
    gather_kernel<<<BB * (NN / 32), 256>>>(ei, out);
}